// round 4
// baseline (speedup 1.0000x reference)
#include <cuda_runtime.h>
#include <math.h>

// ---------------- problem constants ----------------
#define BB   2
#define NN   512
#define HH   12
#define DHD  64
#define DIMD 768
#define DPR  128
#define DCND 512
#define INR  3072
#define NQ   32
#define NK   128
#define NWW  16          // NN / NQ
#define MROWS (BB*NN)    // 1024

// ---------------- scratch ----------------
#define OFF_CN    0L
#define OFF_COND  (OFF_CN   + (long)MROWS*DCND)          // 1024*512
#define OFF_XM    (OFF_COND + (long)MROWS*6*DIMD)        // 1024*4608
#define OFF_XA    (OFF_XM   + (long)MROWS*DIMD)
#define OFF_QKVG  (OFF_XA   + (long)MROWS*DIMD)
#define OFF_QR    (OFF_QKVG + (long)MROWS*4*DIMD)
#define OFF_KR    (OFF_QR   + (long)MROWS*DIMD)
#define OFF_VR    (OFF_KR   + (long)MROWS*DIMD)
#define OFF_BIAS  (OFF_VR   + (long)MROWS*DIMD)
#define OFF_OG    (OFF_BIAS + (long)BB*NWW*NQ*NK*HH)
#define OFF_X1    (OFF_OG   + (long)MROWS*DIMD)
#define OFF_XT    (OFF_X1   + (long)MROWS*DIMD)
#define OFF_ABUF  (OFF_XT   + (long)MROWS*DIMD)
#define OFF_HID   (OFF_ABUF + (long)MROWS*INR)
#define SCRATCH_TOTAL (OFF_HID + (long)MROWS*INR)

__device__ float g_scratch[SCRATCH_TOTAL];

__device__ __forceinline__ float sigf(float z) { return 1.f / (1.f + expf(-z)); }

// ---------------- block reduce (sum, sumsq), 256 threads ----------------
__device__ __forceinline__ float2 block_reduce2_256(float s, float s2) {
    __shared__ float shs[8], shq[8];
    int lane = threadIdx.x & 31, wp = threadIdx.x >> 5;
#pragma unroll
    for (int o = 16; o; o >>= 1) {
        s  += __shfl_xor_sync(0xffffffffu, s,  o);
        s2 += __shfl_xor_sync(0xffffffffu, s2, o);
    }
    if (lane == 0) { shs[wp] = s; shq[wp] = s2; }
    __syncthreads();
    if (wp == 0) {
        float a = (lane < 8) ? shs[lane] : 0.f;
        float b = (lane < 8) ? shq[lane] : 0.f;
#pragma unroll
        for (int o = 4; o; o >>= 1) {
            a += __shfl_xor_sync(0xffffffffu, a, o);
            b += __shfl_xor_sync(0xffffffffu, b, o);
        }
        if (lane == 0) { shs[0] = a; shq[0] = b; }
    }
    __syncthreads();
    return make_float2(shs[0], shq[0]);
}

// ---------------- LN(cond) ----------------
__global__ void ln_cond_kernel(const float* __restrict__ cond, float* __restrict__ cn) {
    int m = blockIdx.x, t = threadIdx.x;
    const float* row = cond + (long)m * DCND;
    float v0 = row[t], v1 = row[t + 256];
    float2 r = block_reduce2_256(v0 + v1, v0 * v0 + v1 * v1);
    float mean = r.x * (1.f / DCND);
    float var  = r.y * (1.f / DCND) - mean * mean;
    float rstd = rsqrtf(var + 1e-5f);
    cn[(long)m * DCND + t]       = (v0 - mean) * rstd;
    cn[(long)m * DCND + t + 256] = (v1 - mean) * rstd;
}

// ---------------- adaln: xa = (LN(x)*gate + shift)*mask ----------------
__global__ void adaln_kernel(const float* __restrict__ xin, const float* __restrict__ mask,
                             const float* __restrict__ gatep, const float* __restrict__ shiftp,
                             float* __restrict__ xm_out, float* __restrict__ xa_out, int premask) {
    int m = blockIdx.x, t = threadIdx.x;
    const float* row = xin + (long)m * DIMD;
    float mk = mask[m];
    float v[3];
#pragma unroll
    for (int i = 0; i < 3; i++) {
        v[i] = row[t + i * 256];
        if (premask) v[i] *= mk;
    }
    float s = 0.f, s2 = 0.f;
#pragma unroll
    for (int i = 0; i < 3; i++) { s += v[i]; s2 += v[i] * v[i]; }
    float2 r = block_reduce2_256(s, s2);
    float mean = r.x * (1.f / DIMD);
    float var  = r.y * (1.f / DIMD) - mean * mean;
    float rstd = rsqrtf(var + 1e-5f);
#pragma unroll
    for (int i = 0; i < 3; i++) {
        int j = t + i * 256;
        if (xm_out) xm_out[(long)m * DIMD + j] = v[i];
        float g = gatep[(long)m * (6 * DIMD) + j];
        float b = shiftp[(long)m * (6 * DIMD) + j];
        xa_out[(long)m * DIMD + j] = ((v[i] - mean) * rstd * g + b) * mk;
    }
}

// ---------------- per-head LN + RoPE on q/k, rearrange v ----------------
// grid: 1024 (b*N+n), block: 384 (warp = head)
__global__ void qkrope_kernel(const float* __restrict__ qkvg,
                              float* __restrict__ qr, float* __restrict__ kr, float* __restrict__ vr) {
    int m = blockIdx.x;
    int b = m >> 9, n = m & 511;
    int h = threadIdx.x >> 5;
    int lane = threadIdx.x & 31;
    const float* base = qkvg + (long)m * (4 * DIMD) + h * DHD;
    long oo = ((long)(b * HH + h) * NN + n) * DHD;

    // angles: d0 = lane, d1 = lane+32; p = d>>1
    int p0 = lane >> 1, p1 = p0 + 16;
    const float kfac = 9.210340371976184f / 64.f;  // ln(10000)/64
    float ang0 = (float)n * expf(-(float)(2 * p0) * kfac);
    float ang1 = (float)n * expf(-(float)(2 * p1) * kfac);
    float c0 = cosf(ang0), s0 = sinf(ang0);
    float c1 = cosf(ang1), s1 = sinf(ang1);
    bool odd = (lane & 1);

#pragma unroll
    for (int which = 0; which < 2; which++) {   // 0=q, 1=k
        const float* src = base + which * DIMD;
        float v0 = src[lane], v1 = src[lane + 32];
        float s = v0 + v1, sq = v0 * v0 + v1 * v1;
#pragma unroll
        for (int o = 16; o; o >>= 1) {
            s  += __shfl_xor_sync(0xffffffffu, s,  o);
            sq += __shfl_xor_sync(0xffffffffu, sq, o);
        }
        float mean = s * (1.f / DHD);
        float var  = sq * (1.f / DHD) - mean * mean;
        float rstd = rsqrtf(var + 1e-5f);
        v0 = (v0 - mean) * rstd;
        v1 = (v1 - mean) * rstd;
        float o0 = __shfl_xor_sync(0xffffffffu, v0, 1);
        float o1 = __shfl_xor_sync(0xffffffffu, v1, 1);
        float r0 = odd ? (o0 * s0 + v0 * c0) : (v0 * c0 - o0 * s0);
        float r1 = odd ? (o1 * s1 + v1 * c1) : (v1 * c1 - o1 * s1);
        float* dst = (which == 0) ? qr : kr;
        dst[oo + lane] = r0;
        dst[oo + lane + 32] = r1;
    }
    // v passthrough rearrange
    const float* vsrc = base + 2 * DIMD;
    vr[oo + lane] = vsrc[lane];
    vr[oo + lane + 32] = vsrc[lane + 32];
}

// ---------------- pair bias: LN(pair_rep[i,j]) @ wb, windowed only ----------------
// grid: 1024 = (b*16+w)*32+q ; block: 128 (thread = key slot kk)
__global__ void pairbias_kernel(const float* __restrict__ pair_rep, const float* __restrict__ wb,
                                float* __restrict__ biasw) {
    __shared__ float wbs[DPR * HH];
    __shared__ float colsum[HH];
    int t = threadIdx.x;
    for (int i = t; i < DPR * HH; i += 128) wbs[i] = wb[i];
    __syncthreads();
    if (t < HH) {
        float cs = 0.f;
        for (int p = 0; p < DPR; p++) cs += wbs[p * HH + t];
        colsum[t] = cs;
    }
    __syncthreads();
    int blk = blockIdx.x;
    int q = blk & 31, w = (blk >> 5) & 15, b = blk >> 9;
    int i = w * NQ + q;
    int idx = w * NQ - 48 + t;
    int j = min(max(idx, 0), NN - 1);
    const float* xr = pair_rep + (((long)b * NN + i) * NN + j) * DPR;
    float s = 0.f, s2 = 0.f;
    float dot[HH];
#pragma unroll
    for (int h = 0; h < HH; h++) dot[h] = 0.f;
#pragma unroll 4
    for (int p = 0; p < DPR; p += 4) {
        float4 xv = *(const float4*)(xr + p);
        s  += xv.x + xv.y + xv.z + xv.w;
        s2 += xv.x * xv.x + xv.y * xv.y + xv.z * xv.z + xv.w * xv.w;
#pragma unroll
        for (int h = 0; h < HH; h++)
            dot[h] += xv.x * wbs[p * HH + h] + xv.y * wbs[(p + 1) * HH + h]
                    + xv.z * wbs[(p + 2) * HH + h] + xv.w * wbs[(p + 3) * HH + h];
    }
    float mean = s * (1.f / DPR);
    float var  = s2 * (1.f / DPR) - mean * mean;
    float rstd = rsqrtf(var + 1e-5f);
    float* outp = biasw + ((long)blk * NK + t) * HH;
#pragma unroll
    for (int h = 0; h < HH; h++) outp[h] = (dot[h] - mean * colsum[h]) * rstd;
}

// ---------------- windowed attention ----------------
// grid: 384 = b*192 + h*16 + w ; block: 256
__global__ __launch_bounds__(256) void attn_kernel(
    const float* __restrict__ qr, const float* __restrict__ kr, const float* __restrict__ vr,
    const float* __restrict__ pair_mask, const float* __restrict__ biasw,
    const float* __restrict__ qkvg, float* __restrict__ og) {
    __shared__ float q_s[NQ][DHD];
    __shared__ float kv[64][65];
    __shared__ float sc[NQ][NK];
    int blk = blockIdx.x;
    int w = blk & 15;
    int h = (blk >> 4) % 12;
    int b = blk / 192;
    int t = threadIdx.x;
    long bh = (long)(b * HH + h) * NN * DHD;

    for (int e = t; e < NQ * DHD; e += 256) {
        int qq = e >> 6, d = e & 63;
        q_s[qq][d] = qr[bh + (long)(w * NQ + qq) * DHD + d];
    }
    int qrow = t >> 3, klane = t & 7;
    int iglob = w * NQ + qrow;

    for (int half = 0; half < 2; half++) {
        __syncthreads();
        for (int e = t; e < 64 * 64; e += 256) {
            int d = e & 63, kkl = e >> 6;
            int kk = half * 64 + kkl;
            int jn = min(max(w * NQ - 48 + kk, 0), NN - 1);
            kv[kkl][d] = kr[bh + (long)jn * DHD + d];
        }
        __syncthreads();
#pragma unroll
        for (int jj = 0; jj < 8; jj++) {
            int kkl = klane + jj * 8;
            int kk = half * 64 + kkl;
            float dot = 0.f;
#pragma unroll
            for (int d = 0; d < DHD; d++) dot = fmaf(q_s[qrow][d], kv[kkl][d], dot);
            int idxr = w * NQ - 48 + kk;
            bool valid = (idxr >= 0) && (idxr < NN);
            int jn = min(max(idxr, 0), NN - 1);
            float pm = pair_mask[((long)b * NN + iglob) * NN + jn];
            float bv = biasw[(((long)(b * NWW + w) * NQ + qrow) * NK + kk) * HH + h];
            sc[qrow][kk] = (valid && pm > 0.f) ? (dot * 0.125f + bv) : -1e9f;
        }
    }
    __syncthreads();
    // softmax per row; 8 lanes per row
    {
        float vals[16];
        float mx = -3.4e38f;
#pragma unroll
        for (int jj = 0; jj < 16; jj++) {
            vals[jj] = sc[qrow][klane + jj * 8];
            mx = fmaxf(mx, vals[jj]);
        }
#pragma unroll
        for (int o = 4; o; o >>= 1) mx = fmaxf(mx, __shfl_xor_sync(0xffffffffu, mx, o));
        float sm = 0.f;
#pragma unroll
        for (int jj = 0; jj < 16; jj++) { vals[jj] = expf(vals[jj] - mx); sm += vals[jj]; }
#pragma unroll
        for (int o = 4; o; o >>= 1) sm += __shfl_xor_sync(0xffffffffu, sm, o);
        float inv = 1.f / sm;
#pragma unroll
        for (int jj = 0; jj < 16; jj++) sc[qrow][klane + jj * 8] = vals[jj] * inv;
    }
    // out = attn @ V
    int dgrp = t & 7;
    float outv[8];
#pragma unroll
    for (int jj = 0; jj < 8; jj++) outv[jj] = 0.f;
    for (int half = 0; half < 2; half++) {
        __syncthreads();
        for (int e = t; e < 64 * 64; e += 256) {
            int d = e & 63, kkl = e >> 6;
            int kk = half * 64 + kkl;
            int jn = min(max(w * NQ - 48 + kk, 0), NN - 1);
            kv[kkl][d] = vr[bh + (long)jn * DHD + d];
        }
        __syncthreads();
#pragma unroll 8
        for (int kkl = 0; kkl < 64; kkl++) {
            float a = sc[qrow][half * 64 + kkl];
#pragma unroll
            for (int jj = 0; jj < 8; jj++)
                outv[jj] = fmaf(a, kv[kkl][dgrp + jj * 8], outv[jj]);
        }
    }
    int m = b * NN + iglob;
    const float* gp = qkvg + (long)m * (4 * DIMD) + 3 * DIMD + h * DHD;  // sigmoid(gate) precomputed
    float* op = og + (long)m * DIMD + h * DHD;
#pragma unroll
    for (int jj = 0; jj < 8; jj++) {
        int d = dgrp + jj * 8;
        op[d] = outv[jj] * gp[d];
    }
}

// ---------------- generic SGEMM 128x128x8, 8x8 microtile ----------------
// C(M,N) = A(M,K) * B(K,N), B can be 6 concatenated (K,768) matrices along N.
// modes: 0 generic (+bias, optional sigmoid per 768-block), 1 ATTNOUT, 2 TRANS_G, 3 TROUT
struct GemmP {
    const float* A; int lda;
    const float* Bp[6]; int ldb;
    const float* biasp[6];
    int sig[6];
    int multi;
    float* C; int ldc;
    int M, N, K;
    int mode;
    const float* e1; int e1ld;   // scale (sigmoid) table
    const float* e2;             // residual (stride DIMD)
    const float* e3;             // mask per row m
    const float* e4; int e4ld;   // a_buf for TRANS_G
};

__global__ void __launch_bounds__(256) sgemm_kernel(GemmP p) {
    __shared__ float As[8][128];
    __shared__ float Bs[8][128];
    const int tid = threadIdx.x;
    const int tx = tid & 15, ty = tid >> 4;
    const int row0 = blockIdx.y * 128, col0 = blockIdx.x * 128;
    int wblk = 0;
    const float* Bbase;
    if (p.multi) { wblk = col0 / 768; Bbase = p.Bp[wblk] + (col0 - wblk * 768); }
    else         { Bbase = p.Bp[0] + col0; }
    const float* Abase = p.A + (long)row0 * p.lda;
    const int arow = tid >> 1, acol = (tid & 1) << 2;
    const int brow = tid >> 5, bcol = (tid & 31) << 2;
    const float* aptr = Abase + (long)arow * p.lda + acol;
    const float* bptr = Bbase + (long)brow * p.ldb + bcol;

    float acc[8][8];
#pragma unroll
    for (int i = 0; i < 8; i++)
#pragma unroll
        for (int j = 0; j < 8; j++) acc[i][j] = 0.f;

    const int nk = p.K >> 3;
    float4 av = *(const float4*)aptr;
    float4 bv = *(const float4*)bptr;
    for (int tk = 0; tk < nk; tk++) {
        As[acol][arow]     = av.x;
        As[acol + 1][arow] = av.y;
        As[acol + 2][arow] = av.z;
        As[acol + 3][arow] = av.w;
        *(float4*)&Bs[brow][bcol] = bv;
        __syncthreads();
        if (tk + 1 < nk) {
            av = *(const float4*)(aptr + (tk + 1) * 8);
            bv = *(const float4*)(bptr + (long)(tk + 1) * 8 * p.ldb);
        }
#pragma unroll
        for (int kk = 0; kk < 8; kk++) {
            float a[8], b[8];
#pragma unroll
            for (int i = 0; i < 8; i++) a[i] = As[kk][ty * 8 + i];
#pragma unroll
            for (int j = 0; j < 8; j++) b[j] = Bs[kk][tx * 8 + j];
#pragma unroll
            for (int i = 0; i < 8; i++)
#pragma unroll
                for (int j = 0; j < 8; j++)
                    acc[i][j] = fmaf(a[i], b[j], acc[i][j]);
        }
        __syncthreads();
    }

    const int m0 = row0 + ty * 8;
    const int n0 = col0 + tx * 8;
    if (p.mode == 0) {
        const float* bias = p.biasp[wblk];
        int dosig = p.sig[wblk];
#pragma unroll
        for (int i = 0; i < 8; i++) {
            int m = m0 + i;
#pragma unroll
            for (int j = 0; j < 8; j++) {
                int n = n0 + j;
                int bn = p.multi ? (n - wblk * 768) : n;
                float z = acc[i][j] + (bias ? bias[bn] : 0.f);
                if (dosig) z = sigf(z);
                p.C[(long)m * p.ldc + n] = z;
            }
        }
    } else if (p.mode == 1) {  // ATTNOUT: x1 = (((acc+bo)*s1*mk*mk) + xm)*mk
        const float* bias = p.biasp[0];
#pragma unroll
        for (int i = 0; i < 8; i++) {
            int m = m0 + i;
            float mk = p.e3[m];
#pragma unroll
            for (int j = 0; j < 8; j++) {
                int n = n0 + j;
                float z = acc[i][j] + bias[n];
                float s = p.e1[(long)m * p.e1ld + n];
                float a1 = z * s * mk * mk;
                p.C[(long)m * p.ldc + n] = (a1 + p.e2[(long)m * DIMD + n]) * mk;
            }
        }
    } else if (p.mode == 2) {  // TRANS_G: hidden = a_buf * silu(acc)
#pragma unroll
        for (int i = 0; i < 8; i++) {
            int m = m0 + i;
#pragma unroll
            for (int j = 0; j < 8; j++) {
                int n = n0 + j;
                float z = acc[i][j];
                float sg = sigf(z);
                p.C[(long)m * p.ldc + n] = p.e4[(long)m * p.e4ld + n] * z * sg;
            }
        }
    } else {  // TROUT: out = (((acc*mk)*s2*mk*mk + x1)*mk)*mk
#pragma unroll
        for (int i = 0; i < 8; i++) {
            int m = m0 + i;
            float mk = p.e3[m];
#pragma unroll
            for (int j = 0; j < 8; j++) {
                int n = n0 + j;
                float t0 = acc[i][j] * mk;
                float s = p.e1[(long)m * p.e1ld + n];
                float t1 = t0 * s * mk * mk;
                p.C[(long)m * p.ldc + n] = ((t1 + p.e2[(long)m * DIMD + n]) * mk) * mk;
            }
        }
    }
}

// ---------------- host launch ----------------
extern "C" void kernel_launch(void* const* d_in, const int* in_sizes, int n_in,
                              void* d_out, int out_size) {
    const float* x         = (const float*)d_in[0];
    const float* pair_rep  = (const float*)d_in[1];
    const float* cond      = (const float*)d_in[2];
    const float* mask      = (const float*)d_in[3];
    const float* pair_mask = (const float*)d_in[4];
    const float* adaln1_gw = (const float*)d_in[5];
    const float* adaln1_gb = (const float*)d_in[6];
    const float* adaln1_bw = (const float*)d_in[7];
    const float* wq = (const float*)d_in[8],  *bq = (const float*)d_in[9];
    const float* wk = (const float*)d_in[10], *bk = (const float*)d_in[11];
    const float* wv = (const float*)d_in[12], *bv = (const float*)d_in[13];
    const float* wg = (const float*)d_in[14], *bg = (const float*)d_in[15];
    const float* wb_pair = (const float*)d_in[16];
    const float* wo = (const float*)d_in[17], *bo = (const float*)d_in[18];
    const float* scale1_w = (const float*)d_in[19], *scale1_b = (const float*)d_in[20];
    const float* adaln2_gw = (const float*)d_in[21], *adaln2_gb = (const float*)d_in[22];
    const float* adaln2_bw = (const float*)d_in[23];
    const float* tr_win  = (const float*)d_in[24];
    const float* tr_wout = (const float*)d_in[25];
    const float* scale2_w = (const float*)d_in[26], *scale2_b = (const float*)d_in[27];

    float* S = nullptr;
    cudaGetSymbolAddress((void**)&S, g_scratch);
    float* cn       = S + OFF_CN;
    float* cond_out = S + OFF_COND;
    float* xm       = S + OFF_XM;
    float* xa       = S + OFF_XA;
    float* qkvg     = S + OFF_QKVG;
    float* qr       = S + OFF_QR;
    float* kr       = S + OFF_KR;
    float* vr       = S + OFF_VR;
    float* biasw    = S + OFF_BIAS;
    float* og       = S + OFF_OG;
    float* x1       = S + OFF_X1;
    float* xt       = S + OFF_XT;
    float* a_buf    = S + OFF_ABUF;
    float* hidden   = S + OFF_HID;

    // 1. LN(cond)
    ln_cond_kernel<<<MROWS, 256>>>(cond, cn);

    // 2. all 6 cond projections in one GEMM: [g1|b1|s1|g2|b2|s2]
    {
        GemmP p = {};
        p.A = cn; p.lda = DCND; p.ldb = DIMD;
        p.Bp[0] = adaln1_gw; p.Bp[1] = adaln1_bw; p.Bp[2] = scale1_w;
        p.Bp[3] = adaln2_gw; p.Bp[4] = adaln2_bw; p.Bp[5] = scale2_w;
        p.biasp[0] = adaln1_gb; p.biasp[1] = nullptr; p.biasp[2] = scale1_b;
        p.biasp[3] = adaln2_gb; p.biasp[4] = nullptr; p.biasp[5] = scale2_b;
        p.sig[0] = 1; p.sig[1] = 0; p.sig[2] = 1; p.sig[3] = 1; p.sig[4] = 0; p.sig[5] = 1;
        p.multi = 1; p.C = cond_out; p.ldc = 6 * DIMD;
        p.M = MROWS; p.N = 6 * DIMD; p.K = DCND; p.mode = 0;
        sgemm_kernel<<<dim3((6 * DIMD) / 128, MROWS / 128), 256>>>(p);
    }

    // 3. xa = adaln1(x)
    adaln_kernel<<<MROWS, 256>>>(x, mask, cond_out, cond_out + DIMD, xm, xa, 1);

    // 4. QKVG projection (gate block gets sigmoid in epilogue)
    {
        GemmP p = {};
        p.A = xa; p.lda = DIMD; p.ldb = DIMD;
        p.Bp[0] = wq; p.Bp[1] = wk; p.Bp[2] = wv; p.Bp[3] = wg;
        p.biasp[0] = bq; p.biasp[1] = bk; p.biasp[2] = bv; p.biasp[3] = bg;
        p.sig[0] = 0; p.sig[1] = 0; p.sig[2] = 0; p.sig[3] = 1;
        p.multi = 1; p.C = qkvg; p.ldc = 4 * DIMD;
        p.M = MROWS; p.N = 4 * DIMD; p.K = DIMD; p.mode = 0;
        sgemm_kernel<<<dim3((4 * DIMD) / 128, MROWS / 128), 256>>>(p);
    }

    // 5. per-head LN + RoPE
    qkrope_kernel<<<MROWS, 384>>>(qkvg, qr, kr, vr);

    // 6. windowed pair bias (only 1/4 of pair_rep read)
    pairbias_kernel<<<BB * NWW * NQ, 128>>>(pair_rep, wb_pair, biasw);

    // 7. windowed attention + gating
    attn_kernel<<<BB * HH * NWW, 256>>>(qr, kr, vr, pair_mask, biasw, qkvg, og);

    // 8. wo GEMM + scale1 + residual -> x1
    {
        GemmP p = {};
        p.A = og; p.lda = DIMD; p.ldb = DIMD;
        p.Bp[0] = wo; p.biasp[0] = bo; p.multi = 0;
        p.C = x1; p.ldc = DIMD;
        p.M = MROWS; p.N = DIMD; p.K = DIMD; p.mode = 1;
        p.e1 = cond_out + 2 * DIMD; p.e1ld = 6 * DIMD;
        p.e2 = xm; p.e3 = mask;
        sgemm_kernel<<<dim3(DIMD / 128, MROWS / 128), 256>>>(p);
    }

    // 9. xt = adaln2(x1)
    adaln_kernel<<<MROWS, 256>>>(x1, mask, cond_out + 3 * DIMD, cond_out + 4 * DIMD, nullptr, xt, 0);

    // 10. transition in: a = xt @ W_a
    {
        GemmP p = {};
        p.A = xt; p.lda = DIMD; p.ldb = 2 * INR;
        p.Bp[0] = tr_win; p.multi = 0;
        p.C = a_buf; p.ldc = INR;
        p.M = MROWS; p.N = INR; p.K = DIMD; p.mode = 0;
        sgemm_kernel<<<dim3(INR / 128, MROWS / 128), 256>>>(p);
    }
    // 11. g = xt @ W_g ; hidden = a * silu(g)
    {
        GemmP p = {};
        p.A = xt; p.lda = DIMD; p.ldb = 2 * INR;
        p.Bp[0] = tr_win + INR; p.multi = 0;
        p.C = hidden; p.ldc = INR;
        p.M = MROWS; p.N = INR; p.K = DIMD; p.mode = 2;
        p.e4 = a_buf; p.e4ld = INR;
        sgemm_kernel<<<dim3(INR / 128, MROWS / 128), 256>>>(p);
    }
    // 12. transition out + scale2 + residual -> d_out
    {
        GemmP p = {};
        p.A = hidden; p.lda = INR; p.ldb = DIMD;
        p.Bp[0] = tr_wout; p.multi = 0;
        p.C = (float*)d_out; p.ldc = DIMD;
        p.M = MROWS; p.N = DIMD; p.K = INR; p.mode = 3;
        p.e1 = cond_out + 5 * DIMD; p.e1ld = 6 * DIMD;
        p.e2 = x1; p.e3 = mask;
        sgemm_kernel<<<dim3(DIMD / 128, MROWS / 128), 256>>>(p);
    }
}

// round 5
// speedup vs baseline: 1.4398x; 1.4398x over previous
#include <cuda_runtime.h>
#include <math.h>

// ---------------- problem constants ----------------
#define BB   2
#define NN   512
#define HH   12
#define DHD  64
#define DIMD 768
#define DPR  128
#define DCND 512
#define INR  3072
#define NQ   32
#define NK   128
#define NWW  16          // NN / NQ
#define MROWS (BB*NN)    // 1024

// ---------------- scratch ----------------
#define OFF_CN    0L
#define OFF_COND  (OFF_CN   + (long)MROWS*DCND)
#define OFF_XM    (OFF_COND + (long)MROWS*6*DIMD)
#define OFF_XA    (OFF_XM   + (long)MROWS*DIMD)
#define OFF_QKVG  (OFF_XA   + (long)MROWS*DIMD)
#define OFF_QR    (OFF_QKVG + (long)MROWS*4*DIMD)
#define OFF_KR    (OFF_QR   + (long)MROWS*DIMD)
#define OFF_VR    (OFF_KR   + (long)MROWS*DIMD)
#define OFF_BIAS  (OFF_VR   + (long)MROWS*DIMD)
#define OFF_OG    (OFF_BIAS + (long)BB*NWW*NQ*NK*HH)
#define OFF_X1    (OFF_OG   + (long)MROWS*DIMD)
#define OFF_XT    (OFF_X1   + (long)MROWS*DIMD)
#define OFF_ABUF  (OFF_XT   + (long)MROWS*DIMD)
#define OFF_HID   (OFF_ABUF + (long)MROWS*INR)
#define OFF_PART  (OFF_HID  + (long)MROWS*INR)
#define SCRATCH_TOTAL (OFF_PART + 3L*MROWS*DIMD)

__device__ float g_scratch[SCRATCH_TOTAL];

__device__ __forceinline__ float sigf(float z) { return 1.f / (1.f + expf(-z)); }

// ---------------- block reduce (sum, sumsq), 256 threads ----------------
__device__ __forceinline__ float2 block_reduce2_256(float s, float s2) {
    __shared__ float shs[8], shq[8];
    int lane = threadIdx.x & 31, wp = threadIdx.x >> 5;
#pragma unroll
    for (int o = 16; o; o >>= 1) {
        s  += __shfl_xor_sync(0xffffffffu, s,  o);
        s2 += __shfl_xor_sync(0xffffffffu, s2, o);
    }
    if (lane == 0) { shs[wp] = s; shq[wp] = s2; }
    __syncthreads();
    if (wp == 0) {
        float a = (lane < 8) ? shs[lane] : 0.f;
        float b = (lane < 8) ? shq[lane] : 0.f;
#pragma unroll
        for (int o = 4; o; o >>= 1) {
            a += __shfl_xor_sync(0xffffffffu, a, o);
            b += __shfl_xor_sync(0xffffffffu, b, o);
        }
        if (lane == 0) { shs[0] = a; shq[0] = b; }
    }
    __syncthreads();
    return make_float2(shs[0], shq[0]);
}

// ---------------- LN(cond) ----------------
__global__ void ln_cond_kernel(const float* __restrict__ cond, float* __restrict__ cn) {
    int m = blockIdx.x, t = threadIdx.x;
    const float* row = cond + (long)m * DCND;
    float v0 = row[t], v1 = row[t + 256];
    float2 r = block_reduce2_256(v0 + v1, v0 * v0 + v1 * v1);
    float mean = r.x * (1.f / DCND);
    float var  = r.y * (1.f / DCND) - mean * mean;
    float rstd = rsqrtf(var + 1e-5f);
    cn[(long)m * DCND + t]       = (v0 - mean) * rstd;
    cn[(long)m * DCND + t + 256] = (v1 - mean) * rstd;
}

// ---------------- adaln ----------------
__global__ void adaln_kernel(const float* __restrict__ xin, const float* __restrict__ mask,
                             const float* __restrict__ gatep, const float* __restrict__ shiftp,
                             float* __restrict__ xm_out, float* __restrict__ xa_out, int premask) {
    int m = blockIdx.x, t = threadIdx.x;
    const float* row = xin + (long)m * DIMD;
    float mk = mask[m];
    float v[3];
#pragma unroll
    for (int i = 0; i < 3; i++) {
        v[i] = row[t + i * 256];
        if (premask) v[i] *= mk;
    }
    float s = 0.f, s2 = 0.f;
#pragma unroll
    for (int i = 0; i < 3; i++) { s += v[i]; s2 += v[i] * v[i]; }
    float2 r = block_reduce2_256(s, s2);
    float mean = r.x * (1.f / DIMD);
    float var  = r.y * (1.f / DIMD) - mean * mean;
    float rstd = rsqrtf(var + 1e-5f);
#pragma unroll
    for (int i = 0; i < 3; i++) {
        int j = t + i * 256;
        if (xm_out) xm_out[(long)m * DIMD + j] = v[i];
        float g = gatep[(long)m * (6 * DIMD) + j];
        float b = shiftp[(long)m * (6 * DIMD) + j];
        xa_out[(long)m * DIMD + j] = ((v[i] - mean) * rstd * g + b) * mk;
    }
}

// ---------------- per-head LN + RoPE ----------------
__global__ void qkrope_kernel(const float* __restrict__ qkvg,
                              float* __restrict__ qr, float* __restrict__ kr, float* __restrict__ vr) {
    int m = blockIdx.x;
    int b = m >> 9, n = m & 511;
    int h = threadIdx.x >> 5;
    int lane = threadIdx.x & 31;
    const float* base = qkvg + (long)m * (4 * DIMD) + h * DHD;
    long oo = ((long)(b * HH + h) * NN + n) * DHD;

    int p0 = lane >> 1, p1 = p0 + 16;
    const float kfac = 9.210340371976184f / 64.f;
    float ang0 = (float)n * expf(-(float)(2 * p0) * kfac);
    float ang1 = (float)n * expf(-(float)(2 * p1) * kfac);
    float c0 = cosf(ang0), s0 = sinf(ang0);
    float c1 = cosf(ang1), s1 = sinf(ang1);
    bool odd = (lane & 1);

#pragma unroll
    for (int which = 0; which < 2; which++) {
        const float* src = base + which * DIMD;
        float v0 = src[lane], v1 = src[lane + 32];
        float s = v0 + v1, sq = v0 * v0 + v1 * v1;
#pragma unroll
        for (int o = 16; o; o >>= 1) {
            s  += __shfl_xor_sync(0xffffffffu, s,  o);
            sq += __shfl_xor_sync(0xffffffffu, sq, o);
        }
        float mean = s * (1.f / DHD);
        float var  = sq * (1.f / DHD) - mean * mean;
        float rstd = rsqrtf(var + 1e-5f);
        v0 = (v0 - mean) * rstd;
        v1 = (v1 - mean) * rstd;
        float o0 = __shfl_xor_sync(0xffffffffu, v0, 1);
        float o1 = __shfl_xor_sync(0xffffffffu, v1, 1);
        float r0 = odd ? (o0 * s0 + v0 * c0) : (v0 * c0 - o0 * s0);
        float r1 = odd ? (o1 * s1 + v1 * c1) : (v1 * c1 - o1 * s1);
        float* dst = (which == 0) ? qr : kr;
        dst[oo + lane] = r0;
        dst[oo + lane + 32] = r1;
    }
    const float* vsrc = base + 2 * DIMD;
    vr[oo + lane] = vsrc[lane];
    vr[oo + lane + 32] = vsrc[lane + 32];
}

// ---------------- pair bias (windowed only) ----------------
__global__ void pairbias_kernel(const float* __restrict__ pair_rep, const float* __restrict__ wb,
                                float* __restrict__ biasw) {
    __shared__ float wbs[DPR * HH];
    __shared__ float colsum[HH];
    int t = threadIdx.x;
    for (int i = t; i < DPR * HH; i += 128) wbs[i] = wb[i];
    __syncthreads();
    if (t < HH) {
        float cs = 0.f;
        for (int p = 0; p < DPR; p++) cs += wbs[p * HH + t];
        colsum[t] = cs;
    }
    __syncthreads();
    int blk = blockIdx.x;
    int q = blk & 31, w = (blk >> 5) & 15, b = blk >> 9;
    int i = w * NQ + q;
    int idx = w * NQ - 48 + t;
    int j = min(max(idx, 0), NN - 1);
    const float* xr = pair_rep + (((long)b * NN + i) * NN + j) * DPR;
    float s = 0.f, s2 = 0.f;
    float dot[HH];
#pragma unroll
    for (int h = 0; h < HH; h++) dot[h] = 0.f;
#pragma unroll 4
    for (int p = 0; p < DPR; p += 4) {
        float4 xv = *(const float4*)(xr + p);
        s  += xv.x + xv.y + xv.z + xv.w;
        s2 += xv.x * xv.x + xv.y * xv.y + xv.z * xv.z + xv.w * xv.w;
#pragma unroll
        for (int h = 0; h < HH; h++)
            dot[h] += xv.x * wbs[p * HH + h] + xv.y * wbs[(p + 1) * HH + h]
                    + xv.z * wbs[(p + 2) * HH + h] + xv.w * wbs[(p + 3) * HH + h];
    }
    float mean = s * (1.f / DPR);
    float var  = s2 * (1.f / DPR) - mean * mean;
    float rstd = rsqrtf(var + 1e-5f);
    float* outp = biasw + ((long)blk * NK + t) * HH;
#pragma unroll
    for (int h = 0; h < HH; h++) outp[h] = (dot[h] - mean * colsum[h]) * rstd;
}

// ---------------- windowed attention ----------------
__global__ __launch_bounds__(256) void attn_kernel(
    const float* __restrict__ qr, const float* __restrict__ kr, const float* __restrict__ vr,
    const float* __restrict__ pair_mask, const float* __restrict__ biasw,
    const float* __restrict__ qkvg, float* __restrict__ og) {
    __shared__ float q_s[NQ][DHD];
    __shared__ float kv[64][65];
    __shared__ float sc[NQ][NK];
    int blk = blockIdx.x;
    int w = blk & 15;
    int h = (blk >> 4) % 12;
    int b = blk / 192;
    int t = threadIdx.x;
    long bh = (long)(b * HH + h) * NN * DHD;

    for (int e = t; e < NQ * DHD; e += 256) {
        int qq = e >> 6, d = e & 63;
        q_s[qq][d] = qr[bh + (long)(w * NQ + qq) * DHD + d];
    }
    int qrow = t >> 3, klane = t & 7;
    int iglob = w * NQ + qrow;

    for (int half = 0; half < 2; half++) {
        __syncthreads();
        for (int e = t; e < 64 * 64; e += 256) {
            int d = e & 63, kkl = e >> 6;
            int kk = half * 64 + kkl;
            int jn = min(max(w * NQ - 48 + kk, 0), NN - 1);
            kv[kkl][d] = kr[bh + (long)jn * DHD + d];
        }
        __syncthreads();
#pragma unroll
        for (int jj = 0; jj < 8; jj++) {
            int kkl = klane + jj * 8;
            int kk = half * 64 + kkl;
            float dot = 0.f;
#pragma unroll
            for (int d = 0; d < DHD; d++) dot = fmaf(q_s[qrow][d], kv[kkl][d], dot);
            int idxr = w * NQ - 48 + kk;
            bool valid = (idxr >= 0) && (idxr < NN);
            int jn = min(max(idxr, 0), NN - 1);
            float pm = pair_mask[((long)b * NN + iglob) * NN + jn];
            float bv = biasw[(((long)(b * NWW + w) * NQ + qrow) * NK + kk) * HH + h];
            sc[qrow][kk] = (valid && pm > 0.f) ? (dot * 0.125f + bv) : -1e9f;
        }
    }
    __syncthreads();
    {
        float vals[16];
        float mx = -3.4e38f;
#pragma unroll
        for (int jj = 0; jj < 16; jj++) {
            vals[jj] = sc[qrow][klane + jj * 8];
            mx = fmaxf(mx, vals[jj]);
        }
#pragma unroll
        for (int o = 4; o; o >>= 1) mx = fmaxf(mx, __shfl_xor_sync(0xffffffffu, mx, o));
        float sm = 0.f;
#pragma unroll
        for (int jj = 0; jj < 16; jj++) { vals[jj] = expf(vals[jj] - mx); sm += vals[jj]; }
#pragma unroll
        for (int o = 4; o; o >>= 1) sm += __shfl_xor_sync(0xffffffffu, sm, o);
        float inv = 1.f / sm;
#pragma unroll
        for (int jj = 0; jj < 16; jj++) sc[qrow][klane + jj * 8] = vals[jj] * inv;
    }
    int dgrp = t & 7;
    float outv[8];
#pragma unroll
    for (int jj = 0; jj < 8; jj++) outv[jj] = 0.f;
    for (int half = 0; half < 2; half++) {
        __syncthreads();
        for (int e = t; e < 64 * 64; e += 256) {
            int d = e & 63, kkl = e >> 6;
            int kk = half * 64 + kkl;
            int jn = min(max(w * NQ - 48 + kk, 0), NN - 1);
            kv[kkl][d] = vr[bh + (long)jn * DHD + d];
        }
        __syncthreads();
#pragma unroll 8
        for (int kkl = 0; kkl < 64; kkl++) {
            float a = sc[qrow][half * 64 + kkl];
#pragma unroll
            for (int jj = 0; jj < 8; jj++)
                outv[jj] = fmaf(a, kv[kkl][dgrp + jj * 8], outv[jj]);
        }
    }
    int m = b * NN + iglob;
    const float* gp = qkvg + (long)m * (4 * DIMD) + 3 * DIMD + h * DHD;
    float* op = og + (long)m * DIMD + h * DHD;
#pragma unroll
    for (int jj = 0; jj < 8; jj++) {
        int d = dgrp + jj * 8;
        op[d] = outv[jj] * gp[d];
    }
}

// ---------------- FFMA2 SGEMM: 64x128 tile, KT=16, double-buffered, fma.rn.f32x2 ----------------
struct GemmP {
    const float* A; int lda;
    const float* Bp[6]; int ldb;
    const float* biasp[6];
    int sig[6];
    int multi;
    float* C; int ldc;
    int M, N, K;
    int mode;          // 0 generic(+bias,+sig), 2 TRANS_G  (splitk>1 -> raw partial store)
    int splitk;
    const float* e4; int e4ld;  // a_buf for mode 2
};

#define GBM 64
#define GBN 128
#define GKT 16

__global__ void __launch_bounds__(256, 2) gemm2_kernel(GemmP p) {
    __shared__ float As2[2][GKT][2 * GBM];   // A duplicated (a,a) pairs
    __shared__ float Bs[2][GKT][GBN];
    const int tid = threadIdx.x;
    const int tx = tid & 15, ty = tid >> 4;
    const int row0 = blockIdx.y * GBM, col0 = blockIdx.x * GBN;
    const int ks = blockIdx.z;
    const int Kper = p.K / p.splitk;
    const int k0 = ks * Kper;

    int wblk = 0;
    const float* Bbase;
    if (p.multi) { wblk = col0 / 768; Bbase = p.Bp[wblk] + (col0 - wblk * 768); }
    else         { Bbase = p.Bp[0] + col0; }

    const int arow = tid >> 2, akq = (tid & 3) * 4;
    const int bkr = tid >> 5, bcol = (tid & 31) * 4;
    const float* aptr  = p.A + (long)(row0 + arow) * p.lda + k0 + akq;
    const float* bptr0 = Bbase + (long)(k0 + bkr) * p.ldb + bcol;
    const float* bptr1 = Bbase + (long)(k0 + bkr + 8) * p.ldb + bcol;

    unsigned long long acc[4][4];
#pragma unroll
    for (int i = 0; i < 4; i++)
#pragma unroll
        for (int j = 0; j < 4; j++) acc[i][j] = 0ull;

    const int nt = Kper / GKT;
    float4 fa, fb0, fb1;
    fa  = *(const float4*)aptr;
    fb0 = *(const float4*)bptr0;
    fb1 = *(const float4*)bptr1;
    // store tile 0
    {
        *(float2*)&As2[0][akq + 0][2 * arow] = make_float2(fa.x, fa.x);
        *(float2*)&As2[0][akq + 1][2 * arow] = make_float2(fa.y, fa.y);
        *(float2*)&As2[0][akq + 2][2 * arow] = make_float2(fa.z, fa.z);
        *(float2*)&As2[0][akq + 3][2 * arow] = make_float2(fa.w, fa.w);
        *(float4*)&Bs[0][bkr][bcol]     = fb0;
        *(float4*)&Bs[0][bkr + 8][bcol] = fb1;
    }
    __syncthreads();

    for (int t = 0; t < nt; t++) {
        const int buf = t & 1;
        if (t + 1 < nt) {
            fa  = *(const float4*)(aptr + (t + 1) * GKT);
            fb0 = *(const float4*)(bptr0 + (long)(t + 1) * GKT * p.ldb);
            fb1 = *(const float4*)(bptr1 + (long)(t + 1) * GKT * p.ldb);
        }
#pragma unroll
        for (int kk = 0; kk < GKT; kk++) {
            ulonglong2 a01 = *(const ulonglong2*)&As2[buf][kk][2 * (ty * 4)];
            ulonglong2 a23 = *(const ulonglong2*)&As2[buf][kk][2 * (ty * 4) + 4];
            ulonglong2 b01 = *(const ulonglong2*)&Bs[buf][kk][tx * 4];
            ulonglong2 b23 = *(const ulonglong2*)&Bs[buf][kk][64 + tx * 4];
            unsigned long long aa[4] = {a01.x, a01.y, a23.x, a23.y};
            unsigned long long bb[4] = {b01.x, b01.y, b23.x, b23.y};
#pragma unroll
            for (int i = 0; i < 4; i++)
#pragma unroll
                for (int j = 0; j < 4; j++)
                    asm("fma.rn.f32x2 %0, %1, %2, %0;"
                        : "+l"(acc[i][j]) : "l"(aa[i]), "l"(bb[j]));
        }
        if (t + 1 < nt) {
            const int nb = buf ^ 1;
            *(float2*)&As2[nb][akq + 0][2 * arow] = make_float2(fa.x, fa.x);
            *(float2*)&As2[nb][akq + 1][2 * arow] = make_float2(fa.y, fa.y);
            *(float2*)&As2[nb][akq + 2][2 * arow] = make_float2(fa.z, fa.z);
            *(float2*)&As2[nb][akq + 3][2 * arow] = make_float2(fa.w, fa.w);
            *(float4*)&Bs[nb][bkr][bcol]     = fb0;
            *(float4*)&Bs[nb][bkr + 8][bcol] = fb1;
            __syncthreads();
        }
    }

    // epilogue
    union U { unsigned long long u; float2 f; };
    if (p.splitk > 1) {
        float* Cp = p.C + (long)ks * p.M * p.N;
#pragma unroll
        for (int i = 0; i < 4; i++) {
            int m = row0 + ty * 4 + i;
#pragma unroll
            for (int j2 = 0; j2 < 4; j2++) {
                int n = col0 + (j2 >> 1) * 64 + tx * 4 + (j2 & 1) * 2;
                U u; u.u = acc[i][j2];
                Cp[(long)m * p.N + n]     = u.f.x;
                Cp[(long)m * p.N + n + 1] = u.f.y;
            }
        }
    } else if (p.mode == 0) {
        const float* bias = p.biasp[wblk];
        int dosig = p.sig[wblk];
#pragma unroll
        for (int i = 0; i < 4; i++) {
            int m = row0 + ty * 4 + i;
#pragma unroll
            for (int j2 = 0; j2 < 4; j2++) {
                int n = col0 + (j2 >> 1) * 64 + tx * 4 + (j2 & 1) * 2;
                U u; u.u = acc[i][j2];
#pragma unroll
                for (int l = 0; l < 2; l++) {
                    int nn = n + l;
                    int bn = p.multi ? (nn - wblk * 768) : nn;
                    float z = (l ? u.f.y : u.f.x) + (bias ? bias[bn] : 0.f);
                    if (dosig) z = sigf(z);
                    p.C[(long)m * p.ldc + nn] = z;
                }
            }
        }
    } else {  // mode 2: hidden = a_buf * silu(acc)
#pragma unroll
        for (int i = 0; i < 4; i++) {
            int m = row0 + ty * 4 + i;
#pragma unroll
            for (int j2 = 0; j2 < 4; j2++) {
                int n = col0 + (j2 >> 1) * 64 + tx * 4 + (j2 & 1) * 2;
                U u; u.u = acc[i][j2];
#pragma unroll
                for (int l = 0; l < 2; l++) {
                    int nn = n + l;
                    float z = l ? u.f.y : u.f.x;
                    p.C[(long)m * p.ldc + nn] = p.e4[(long)m * p.e4ld + nn] * z * sigf(z);
                }
            }
        }
    }
}

// ---------------- split-K reduce + fused epilogue (modes 1 and 3, N=768) ----------------
__global__ void reduce_epi_kernel(const float* __restrict__ part,
                                  const float* __restrict__ bias,
                                  const float* __restrict__ e1, int e1ld,
                                  const float* __restrict__ e2,
                                  const float* __restrict__ mask,
                                  float* __restrict__ C, int mode) {
    int m = blockIdx.x, t = threadIdx.x;
    float mk = mask[m];
    const long MN = (long)MROWS * DIMD;
#pragma unroll
    for (int c = 0; c < 3; c++) {
        int n = t + c * 256;
        long idx = (long)m * DIMD + n;
        float z = part[idx] + part[MN + idx] + part[2 * MN + idx];
        float s = e1[(long)m * e1ld + n];
        float r;
        if (mode == 1) {
            z += bias[n];
            r = (z * s * mk * mk + e2[idx]) * mk;
        } else {
            float t0 = z * mk;
            float t1 = t0 * s * mk * mk;
            r = ((t1 + e2[idx]) * mk) * mk;
        }
        C[idx] = r;
    }
}

// ---------------- host launch ----------------
extern "C" void kernel_launch(void* const* d_in, const int* in_sizes, int n_in,
                              void* d_out, int out_size) {
    const float* x         = (const float*)d_in[0];
    const float* pair_rep  = (const float*)d_in[1];
    const float* cond      = (const float*)d_in[2];
    const float* mask      = (const float*)d_in[3];
    const float* pair_mask = (const float*)d_in[4];
    const float* adaln1_gw = (const float*)d_in[5];
    const float* adaln1_gb = (const float*)d_in[6];
    const float* adaln1_bw = (const float*)d_in[7];
    const float* wq = (const float*)d_in[8],  *bq = (const float*)d_in[9];
    const float* wk = (const float*)d_in[10], *bk = (const float*)d_in[11];
    const float* wv = (const float*)d_in[12], *bv = (const float*)d_in[13];
    const float* wg = (const float*)d_in[14], *bg = (const float*)d_in[15];
    const float* wb_pair = (const float*)d_in[16];
    const float* wo = (const float*)d_in[17], *bo = (const float*)d_in[18];
    const float* scale1_w = (const float*)d_in[19], *scale1_b = (const float*)d_in[20];
    const float* adaln2_gw = (const float*)d_in[21], *adaln2_gb = (const float*)d_in[22];
    const float* adaln2_bw = (const float*)d_in[23];
    const float* tr_win  = (const float*)d_in[24];
    const float* tr_wout = (const float*)d_in[25];
    const float* scale2_w = (const float*)d_in[26], *scale2_b = (const float*)d_in[27];

    float* S = nullptr;
    cudaGetSymbolAddress((void**)&S, g_scratch);
    float* cn       = S + OFF_CN;
    float* cond_out = S + OFF_COND;
    float* xm       = S + OFF_XM;
    float* xa       = S + OFF_XA;
    float* qkvg     = S + OFF_QKVG;
    float* qr       = S + OFF_QR;
    float* kr       = S + OFF_KR;
    float* vr       = S + OFF_VR;
    float* biasw    = S + OFF_BIAS;
    float* og       = S + OFF_OG;
    float* x1       = S + OFF_X1;
    float* xt       = S + OFF_XT;
    float* a_buf    = S + OFF_ABUF;
    float* hidden   = S + OFF_HID;
    float* part     = S + OFF_PART;

    // 1. LN(cond)
    ln_cond_kernel<<<MROWS, 256>>>(cond, cn);

    // 2. six cond projections in one GEMM: [g1|b1|s1|g2|b2|s2]
    {
        GemmP p = {};
        p.A = cn; p.lda = DCND; p.ldb = DIMD;
        p.Bp[0] = adaln1_gw; p.Bp[1] = adaln1_bw; p.Bp[2] = scale1_w;
        p.Bp[3] = adaln2_gw; p.Bp[4] = adaln2_bw; p.Bp[5] = scale2_w;
        p.biasp[0] = adaln1_gb; p.biasp[1] = nullptr; p.biasp[2] = scale1_b;
        p.biasp[3] = adaln2_gb; p.biasp[4] = nullptr; p.biasp[5] = scale2_b;
        p.sig[0] = 1; p.sig[1] = 0; p.sig[2] = 1; p.sig[3] = 1; p.sig[4] = 0; p.sig[5] = 1;
        p.multi = 1; p.C = cond_out; p.ldc = 6 * DIMD;
        p.M = MROWS; p.N = 6 * DIMD; p.K = DCND; p.mode = 0; p.splitk = 1;
        gemm2_kernel<<<dim3((6 * DIMD) / GBN, MROWS / GBM, 1), 256>>>(p);
    }

    // 3. xa = adaln1(x)
    adaln_kernel<<<MROWS, 256>>>(x, mask, cond_out, cond_out + DIMD, xm, xa, 1);

    // 4. QKVG projection (gate block sigmoided in epilogue)
    {
        GemmP p = {};
        p.A = xa; p.lda = DIMD; p.ldb = DIMD;
        p.Bp[0] = wq; p.Bp[1] = wk; p.Bp[2] = wv; p.Bp[3] = wg;
        p.biasp[0] = bq; p.biasp[1] = bk; p.biasp[2] = bv; p.biasp[3] = bg;
        p.sig[0] = 0; p.sig[1] = 0; p.sig[2] = 0; p.sig[3] = 1;
        p.multi = 1; p.C = qkvg; p.ldc = 4 * DIMD;
        p.M = MROWS; p.N = 4 * DIMD; p.K = DIMD; p.mode = 0; p.splitk = 1;
        gemm2_kernel<<<dim3((4 * DIMD) / GBN, MROWS / GBM, 1), 256>>>(p);
    }

    // 5. per-head LN + RoPE
    qkrope_kernel<<<MROWS, 384>>>(qkvg, qr, kr, vr);

    // 6. windowed pair bias
    pairbias_kernel<<<BB * NWW * NQ, 128>>>(pair_rep, wb_pair, biasw);

    // 7. windowed attention + gating
    attn_kernel<<<BB * HH * NWW, 256>>>(qr, kr, vr, pair_mask, biasw, qkvg, og);

    // 8. wo GEMM split-K=3 -> partials, then reduce+epilogue (mode 1) -> x1
    {
        GemmP p = {};
        p.A = og; p.lda = DIMD; p.ldb = DIMD;
        p.Bp[0] = wo; p.multi = 0;
        p.C = part; p.ldc = DIMD;
        p.M = MROWS; p.N = DIMD; p.K = DIMD; p.mode = 0; p.splitk = 3;
        gemm2_kernel<<<dim3(DIMD / GBN, MROWS / GBM, 3), 256>>>(p);
        reduce_epi_kernel<<<MROWS, 256>>>(part, bo, cond_out + 2 * DIMD, 6 * DIMD,
                                          xm, mask, x1, 1);
    }

    // 9. xt = adaln2(x1)
    adaln_kernel<<<MROWS, 256>>>(x1, mask, cond_out + 3 * DIMD, cond_out + 4 * DIMD, nullptr, xt, 0);

    // 10. transition in: a = xt @ W_a
    {
        GemmP p = {};
        p.A = xt; p.lda = DIMD; p.ldb = 2 * INR;
        p.Bp[0] = tr_win; p.multi = 0;
        p.C = a_buf; p.ldc = INR;
        p.M = MROWS; p.N = INR; p.K = DIMD; p.mode = 0; p.splitk = 1;
        gemm2_kernel<<<dim3(INR / GBN, MROWS / GBM, 1), 256>>>(p);
    }
    // 11. g = xt @ W_g ; hidden = a * silu(g)
    {
        GemmP p = {};
        p.A = xt; p.lda = DIMD; p.ldb = 2 * INR;
        p.Bp[0] = tr_win + INR; p.multi = 0;
        p.C = hidden; p.ldc = INR;
        p.M = MROWS; p.N = INR; p.K = DIMD; p.mode = 2; p.splitk = 1;
        p.e4 = a_buf; p.e4ld = INR;
        gemm2_kernel<<<dim3(INR / GBN, MROWS / GBM, 1), 256>>>(p);
    }
    // 12. transition out split-K=3 -> partials, then reduce+epilogue (mode 3) -> d_out
    {
        GemmP p = {};
        p.A = hidden; p.lda = INR; p.ldb = DIMD;
        p.Bp[0] = tr_wout; p.multi = 0;
        p.C = part; p.ldc = DIMD;
        p.M = MROWS; p.N = DIMD; p.K = INR; p.mode = 0; p.splitk = 3;
        gemm2_kernel<<<dim3(DIMD / GBN, MROWS / GBM, 3), 256>>>(p);
        reduce_epi_kernel<<<MROWS, 256>>>(part, nullptr, cond_out + 5 * DIMD, 6 * DIMD,
                                          x1, mask, (float*)d_out, 3);
    }
}

// round 6
// speedup vs baseline: 1.4399x; 1.0001x over previous
#include <cuda_runtime.h>
#include <math.h>

// ---------------- problem constants ----------------
#define BB   2
#define NN   512
#define HH   12
#define DHD  64
#define DIMD 768
#define DPR  128
#define DCND 512
#define INR  3072
#define NQ   32
#define NK   128
#define NWW  16          // NN / NQ
#define MROWS (BB*NN)    // 1024

// ---------------- scratch ----------------
#define OFF_CN    0L
#define OFF_COND  (OFF_CN   + (long)MROWS*DCND)
#define OFF_XM    (OFF_COND + (long)MROWS*6*DIMD)
#define OFF_XA    (OFF_XM   + (long)MROWS*DIMD)
#define OFF_QKVG  (OFF_XA   + (long)MROWS*DIMD)
#define OFF_QR    (OFF_QKVG + (long)MROWS*4*DIMD)
#define OFF_KR    (OFF_QR   + (long)MROWS*DIMD)
#define OFF_VR    (OFF_KR   + (long)MROWS*DIMD)
#define OFF_BIAS  (OFF_VR   + (long)MROWS*DIMD)
#define OFF_OG    (OFF_BIAS + (long)BB*NWW*NQ*NK*HH)
#define OFF_X1    (OFF_OG   + (long)MROWS*DIMD)
#define OFF_XT    (OFF_X1   + (long)MROWS*DIMD)
#define OFF_ABUF  (OFF_XT   + (long)MROWS*DIMD)
#define OFF_HID   (OFF_ABUF + (long)MROWS*INR)
#define OFF_PART  (OFF_HID  + (long)MROWS*INR)
#define SCRATCH_TOTAL (OFF_PART + 3L*MROWS*DIMD)

__device__ float g_scratch[SCRATCH_TOTAL];

__device__ __forceinline__ float sigf(float z) { return 1.f / (1.f + expf(-z)); }

// ---------------- block reduce (sum, sumsq), 256 threads ----------------
__device__ __forceinline__ float2 block_reduce2_256(float s, float s2) {
    __shared__ float shs[8], shq[8];
    int lane = threadIdx.x & 31, wp = threadIdx.x >> 5;
#pragma unroll
    for (int o = 16; o; o >>= 1) {
        s  += __shfl_xor_sync(0xffffffffu, s,  o);
        s2 += __shfl_xor_sync(0xffffffffu, s2, o);
    }
    if (lane == 0) { shs[wp] = s; shq[wp] = s2; }
    __syncthreads();
    if (wp == 0) {
        float a = (lane < 8) ? shs[lane] : 0.f;
        float b = (lane < 8) ? shq[lane] : 0.f;
#pragma unroll
        for (int o = 4; o; o >>= 1) {
            a += __shfl_xor_sync(0xffffffffu, a, o);
            b += __shfl_xor_sync(0xffffffffu, b, o);
        }
        if (lane == 0) { shs[0] = a; shq[0] = b; }
    }
    __syncthreads();
    return make_float2(shs[0], shq[0]);
}

// ---------------- LN(cond) ----------------
__global__ void ln_cond_kernel(const float* __restrict__ cond, float* __restrict__ cn) {
    int m = blockIdx.x, t = threadIdx.x;
    const float* row = cond + (long)m * DCND;
    float v0 = row[t], v1 = row[t + 256];
    float2 r = block_reduce2_256(v0 + v1, v0 * v0 + v1 * v1);
    float mean = r.x * (1.f / DCND);
    float var  = r.y * (1.f / DCND) - mean * mean;
    float rstd = rsqrtf(var + 1e-5f);
    cn[(long)m * DCND + t]       = (v0 - mean) * rstd;
    cn[(long)m * DCND + t + 256] = (v1 - mean) * rstd;
}

// ---------------- adaln ----------------
__global__ void adaln_kernel(const float* __restrict__ xin, const float* __restrict__ mask,
                             const float* __restrict__ gatep, const float* __restrict__ shiftp,
                             float* __restrict__ xm_out, float* __restrict__ xa_out, int premask) {
    int m = blockIdx.x, t = threadIdx.x;
    const float* row = xin + (long)m * DIMD;
    float mk = mask[m];
    float v[3];
#pragma unroll
    for (int i = 0; i < 3; i++) {
        v[i] = row[t + i * 256];
        if (premask) v[i] *= mk;
    }
    float s = 0.f, s2 = 0.f;
#pragma unroll
    for (int i = 0; i < 3; i++) { s += v[i]; s2 += v[i] * v[i]; }
    float2 r = block_reduce2_256(s, s2);
    float mean = r.x * (1.f / DIMD);
    float var  = r.y * (1.f / DIMD) - mean * mean;
    float rstd = rsqrtf(var + 1e-5f);
#pragma unroll
    for (int i = 0; i < 3; i++) {
        int j = t + i * 256;
        if (xm_out) xm_out[(long)m * DIMD + j] = v[i];
        float g = gatep[(long)m * (6 * DIMD) + j];
        float b = shiftp[(long)m * (6 * DIMD) + j];
        xa_out[(long)m * DIMD + j] = ((v[i] - mean) * rstd * g + b) * mk;
    }
}

// ---------------- per-head LN + RoPE ----------------
__global__ void qkrope_kernel(const float* __restrict__ qkvg,
                              float* __restrict__ qr, float* __restrict__ kr, float* __restrict__ vr) {
    int m = blockIdx.x;
    int b = m >> 9, n = m & 511;
    int h = threadIdx.x >> 5;
    int lane = threadIdx.x & 31;
    const float* base = qkvg + (long)m * (4 * DIMD) + h * DHD;
    long oo = ((long)(b * HH + h) * NN + n) * DHD;

    int p0 = lane >> 1, p1 = p0 + 16;
    const float kfac = 9.210340371976184f / 64.f;
    float ang0 = (float)n * expf(-(float)(2 * p0) * kfac);
    float ang1 = (float)n * expf(-(float)(2 * p1) * kfac);
    float c0 = cosf(ang0), s0 = sinf(ang0);
    float c1 = cosf(ang1), s1 = sinf(ang1);
    bool odd = (lane & 1);

#pragma unroll
    for (int which = 0; which < 2; which++) {
        const float* src = base + which * DIMD;
        float v0 = src[lane], v1 = src[lane + 32];
        float s = v0 + v1, sq = v0 * v0 + v1 * v1;
#pragma unroll
        for (int o = 16; o; o >>= 1) {
            s  += __shfl_xor_sync(0xffffffffu, s,  o);
            sq += __shfl_xor_sync(0xffffffffu, sq, o);
        }
        float mean = s * (1.f / DHD);
        float var  = sq * (1.f / DHD) - mean * mean;
        float rstd = rsqrtf(var + 1e-5f);
        v0 = (v0 - mean) * rstd;
        v1 = (v1 - mean) * rstd;
        float o0 = __shfl_xor_sync(0xffffffffu, v0, 1);
        float o1 = __shfl_xor_sync(0xffffffffu, v1, 1);
        float r0 = odd ? (o0 * s0 + v0 * c0) : (v0 * c0 - o0 * s0);
        float r1 = odd ? (o1 * s1 + v1 * c1) : (v1 * c1 - o1 * s1);
        float* dst = (which == 0) ? qr : kr;
        dst[oo + lane] = r0;
        dst[oo + lane + 32] = r1;
    }
    const float* vsrc = base + 2 * DIMD;
    vr[oo + lane] = vsrc[lane];
    vr[oo + lane + 32] = vsrc[lane + 32];
}

// ---------------- pair bias (windowed only) ----------------
__global__ void pairbias_kernel(const float* __restrict__ pair_rep, const float* __restrict__ wb,
                                float* __restrict__ biasw) {
    __shared__ float wbs[DPR * HH];
    __shared__ float colsum[HH];
    int t = threadIdx.x;
    for (int i = t; i < DPR * HH; i += 128) wbs[i] = wb[i];
    __syncthreads();
    if (t < HH) {
        float cs = 0.f;
        for (int p = 0; p < DPR; p++) cs += wbs[p * HH + t];
        colsum[t] = cs;
    }
    __syncthreads();
    int blk = blockIdx.x;
    int q = blk & 31, w = (blk >> 5) & 15, b = blk >> 9;
    int i = w * NQ + q;
    int idx = w * NQ - 48 + t;
    int j = min(max(idx, 0), NN - 1);
    const float* xr = pair_rep + (((long)b * NN + i) * NN + j) * DPR;
    float s = 0.f, s2 = 0.f;
    float dot[HH];
#pragma unroll
    for (int h = 0; h < HH; h++) dot[h] = 0.f;
#pragma unroll 4
    for (int p = 0; p < DPR; p += 4) {
        float4 xv = *(const float4*)(xr + p);
        s  += xv.x + xv.y + xv.z + xv.w;
        s2 += xv.x * xv.x + xv.y * xv.y + xv.z * xv.z + xv.w * xv.w;
#pragma unroll
        for (int h = 0; h < HH; h++)
            dot[h] += xv.x * wbs[p * HH + h] + xv.y * wbs[(p + 1) * HH + h]
                    + xv.z * wbs[(p + 2) * HH + h] + xv.w * wbs[(p + 3) * HH + h];
    }
    float mean = s * (1.f / DPR);
    float var  = s2 * (1.f / DPR) - mean * mean;
    float rstd = rsqrtf(var + 1e-5f);
    float* outp = biasw + ((long)blk * NK + t) * HH;
#pragma unroll
    for (int h = 0; h < HH; h++) outp[h] = (dot[h] - mean * colsum[h]) * rstd;
}

// ---------------- windowed attention ----------------
__global__ __launch_bounds__(256) void attn_kernel(
    const float* __restrict__ qr, const float* __restrict__ kr, const float* __restrict__ vr,
    const float* __restrict__ pair_mask, const float* __restrict__ biasw,
    const float* __restrict__ qkvg, float* __restrict__ og) {
    __shared__ float q_s[NQ][DHD];
    __shared__ float kv[64][65];
    __shared__ float sc[NQ][NK];
    int blk = blockIdx.x;
    int w = blk & 15;
    int h = (blk >> 4) % 12;
    int b = blk / 192;
    int t = threadIdx.x;
    long bh = (long)(b * HH + h) * NN * DHD;

    for (int e = t; e < NQ * DHD; e += 256) {
        int qq = e >> 6, d = e & 63;
        q_s[qq][d] = qr[bh + (long)(w * NQ + qq) * DHD + d];
    }
    int qrow = t >> 3, klane = t & 7;
    int iglob = w * NQ + qrow;

    for (int half = 0; half < 2; half++) {
        __syncthreads();
        for (int e = t; e < 64 * 64; e += 256) {
            int d = e & 63, kkl = e >> 6;
            int kk = half * 64 + kkl;
            int jn = min(max(w * NQ - 48 + kk, 0), NN - 1);
            kv[kkl][d] = kr[bh + (long)jn * DHD + d];
        }
        __syncthreads();
#pragma unroll
        for (int jj = 0; jj < 8; jj++) {
            int kkl = klane + jj * 8;
            int kk = half * 64 + kkl;
            float dot = 0.f;
#pragma unroll
            for (int d = 0; d < DHD; d++) dot = fmaf(q_s[qrow][d], kv[kkl][d], dot);
            int idxr = w * NQ - 48 + kk;
            bool valid = (idxr >= 0) && (idxr < NN);
            int jn = min(max(idxr, 0), NN - 1);
            float pm = pair_mask[((long)b * NN + iglob) * NN + jn];
            float bv = biasw[(((long)(b * NWW + w) * NQ + qrow) * NK + kk) * HH + h];
            sc[qrow][kk] = (valid && pm > 0.f) ? (dot * 0.125f + bv) : -1e9f;
        }
    }
    __syncthreads();
    {
        float vals[16];
        float mx = -3.4e38f;
#pragma unroll
        for (int jj = 0; jj < 16; jj++) {
            vals[jj] = sc[qrow][klane + jj * 8];
            mx = fmaxf(mx, vals[jj]);
        }
#pragma unroll
        for (int o = 4; o; o >>= 1) mx = fmaxf(mx, __shfl_xor_sync(0xffffffffu, mx, o));
        float sm = 0.f;
#pragma unroll
        for (int jj = 0; jj < 16; jj++) { vals[jj] = expf(vals[jj] - mx); sm += vals[jj]; }
#pragma unroll
        for (int o = 4; o; o >>= 1) sm += __shfl_xor_sync(0xffffffffu, sm, o);
        float inv = 1.f / sm;
#pragma unroll
        for (int jj = 0; jj < 16; jj++) sc[qrow][klane + jj * 8] = vals[jj] * inv;
    }
    int dgrp = t & 7;
    float outv[8];
#pragma unroll
    for (int jj = 0; jj < 8; jj++) outv[jj] = 0.f;
    for (int half = 0; half < 2; half++) {
        __syncthreads();
        for (int e = t; e < 64 * 64; e += 256) {
            int d = e & 63, kkl = e >> 6;
            int kk = half * 64 + kkl;
            int jn = min(max(w * NQ - 48 + kk, 0), NN - 1);
            kv[kkl][d] = vr[bh + (long)jn * DHD + d];
        }
        __syncthreads();
#pragma unroll 8
        for (int kkl = 0; kkl < 64; kkl++) {
            float a = sc[qrow][half * 64 + kkl];
#pragma unroll
            for (int jj = 0; jj < 8; jj++)
                outv[jj] = fmaf(a, kv[kkl][dgrp + jj * 8], outv[jj]);
        }
    }
    int m = b * NN + iglob;
    const float* gp = qkvg + (long)m * (4 * DIMD) + 3 * DIMD + h * DHD;
    float* op = og + (long)m * DIMD + h * DHD;
#pragma unroll
    for (int jj = 0; jj < 8; jj++) {
        int d = dgrp + jj * 8;
        op[d] = outv[jj] * gp[d];
    }
}

// ---------------- FFMA2 SGEMM: 64x128 tile, KT=16, double-buffered, fma.rn.f32x2 ----------------
struct GemmP {
    const float* A; int lda;
    const float* Bp[6]; int ldb;
    const float* biasp[6];
    int sig[6];
    int multi;
    float* C; int ldc;
    int M, N, K;
    int mode;          // 0 generic(+bias,+sig), 2 TRANS_G  (splitk>1 -> raw partial store)
    int splitk;
    const float* e4; int e4ld;  // a_buf for mode 2
};

#define GBM 64
#define GBN 128
#define GKT 16

__global__ void __launch_bounds__(256, 2) gemm2_kernel(GemmP p) {
    __shared__ float As2[2][GKT][2 * GBM];   // A duplicated (a,a) pairs
    __shared__ float Bs[2][GKT][GBN];
    const int tid = threadIdx.x;
    const int tx = tid & 15, ty = tid >> 4;
    const int row0 = blockIdx.y * GBM, col0 = blockIdx.x * GBN;
    const int ks = blockIdx.z;
    const int Kper = p.K / p.splitk;
    const int k0 = ks * Kper;

    int wblk = 0;
    const float* Bbase;
    if (p.multi) { wblk = col0 / 768; Bbase = p.Bp[wblk] + (col0 - wblk * 768); }
    else         { Bbase = p.Bp[0] + col0; }

    const int arow = tid >> 2, akq = (tid & 3) * 4;
    const int bkr = tid >> 5, bcol = (tid & 31) * 4;
    const float* aptr  = p.A + (long)(row0 + arow) * p.lda + k0 + akq;
    const float* bptr0 = Bbase + (long)(k0 + bkr) * p.ldb + bcol;
    const float* bptr1 = Bbase + (long)(k0 + bkr + 8) * p.ldb + bcol;

    unsigned long long acc[4][4];
#pragma unroll
    for (int i = 0; i < 4; i++)
#pragma unroll
        for (int j = 0; j < 4; j++) acc[i][j] = 0ull;

    const int nt = Kper / GKT;
    float4 fa, fb0, fb1;
    fa  = *(const float4*)aptr;
    fb0 = *(const float4*)bptr0;
    fb1 = *(const float4*)bptr1;
    // store tile 0
    {
        *(float2*)&As2[0][akq + 0][2 * arow] = make_float2(fa.x, fa.x);
        *(float2*)&As2[0][akq + 1][2 * arow] = make_float2(fa.y, fa.y);
        *(float2*)&As2[0][akq + 2][2 * arow] = make_float2(fa.z, fa.z);
        *(float2*)&As2[0][akq + 3][2 * arow] = make_float2(fa.w, fa.w);
        *(float4*)&Bs[0][bkr][bcol]     = fb0;
        *(float4*)&Bs[0][bkr + 8][bcol] = fb1;
    }
    __syncthreads();

    for (int t = 0; t < nt; t++) {
        const int buf = t & 1;
        if (t + 1 < nt) {
            fa  = *(const float4*)(aptr + (t + 1) * GKT);
            fb0 = *(const float4*)(bptr0 + (long)(t + 1) * GKT * p.ldb);
            fb1 = *(const float4*)(bptr1 + (long)(t + 1) * GKT * p.ldb);
        }
#pragma unroll
        for (int kk = 0; kk < GKT; kk++) {
            ulonglong2 a01 = *(const ulonglong2*)&As2[buf][kk][2 * (ty * 4)];
            ulonglong2 a23 = *(const ulonglong2*)&As2[buf][kk][2 * (ty * 4) + 4];
            ulonglong2 b01 = *(const ulonglong2*)&Bs[buf][kk][tx * 4];
            ulonglong2 b23 = *(const ulonglong2*)&Bs[buf][kk][64 + tx * 4];
            unsigned long long aa[4] = {a01.x, a01.y, a23.x, a23.y};
            unsigned long long bb[4] = {b01.x, b01.y, b23.x, b23.y};
#pragma unroll
            for (int i = 0; i < 4; i++)
#pragma unroll
                for (int j = 0; j < 4; j++)
                    asm("fma.rn.f32x2 %0, %1, %2, %0;"
                        : "+l"(acc[i][j]) : "l"(aa[i]), "l"(bb[j]));
        }
        if (t + 1 < nt) {
            const int nb = buf ^ 1;
            *(float2*)&As2[nb][akq + 0][2 * arow] = make_float2(fa.x, fa.x);
            *(float2*)&As2[nb][akq + 1][2 * arow] = make_float2(fa.y, fa.y);
            *(float2*)&As2[nb][akq + 2][2 * arow] = make_float2(fa.z, fa.z);
            *(float2*)&As2[nb][akq + 3][2 * arow] = make_float2(fa.w, fa.w);
            *(float4*)&Bs[nb][bkr][bcol]     = fb0;
            *(float4*)&Bs[nb][bkr + 8][bcol] = fb1;
            __syncthreads();
        }
    }

    // epilogue
    union U { unsigned long long u; float2 f; };
    if (p.splitk > 1) {
        float* Cp = p.C + (long)ks * p.M * p.N;
#pragma unroll
        for (int i = 0; i < 4; i++) {
            int m = row0 + ty * 4 + i;
#pragma unroll
            for (int j2 = 0; j2 < 4; j2++) {
                int n = col0 + (j2 >> 1) * 64 + tx * 4 + (j2 & 1) * 2;
                U u; u.u = acc[i][j2];
                Cp[(long)m * p.N + n]     = u.f.x;
                Cp[(long)m * p.N + n + 1] = u.f.y;
            }
        }
    } else if (p.mode == 0) {
        const float* bias = p.biasp[wblk];
        int dosig = p.sig[wblk];
#pragma unroll
        for (int i = 0; i < 4; i++) {
            int m = row0 + ty * 4 + i;
#pragma unroll
            for (int j2 = 0; j2 < 4; j2++) {
                int n = col0 + (j2 >> 1) * 64 + tx * 4 + (j2 & 1) * 2;
                U u; u.u = acc[i][j2];
#pragma unroll
                for (int l = 0; l < 2; l++) {
                    int nn = n + l;
                    int bn = p.multi ? (nn - wblk * 768) : nn;
                    float z = (l ? u.f.y : u.f.x) + (bias ? bias[bn] : 0.f);
                    if (dosig) z = sigf(z);
                    p.C[(long)m * p.ldc + nn] = z;
                }
            }
        }
    } else {  // mode 2: hidden = a_buf * silu(acc)
#pragma unroll
        for (int i = 0; i < 4; i++) {
            int m = row0 + ty * 4 + i;
#pragma unroll
            for (int j2 = 0; j2 < 4; j2++) {
                int n = col0 + (j2 >> 1) * 64 + tx * 4 + (j2 & 1) * 2;
                U u; u.u = acc[i][j2];
#pragma unroll
                for (int l = 0; l < 2; l++) {
                    int nn = n + l;
                    float z = l ? u.f.y : u.f.x;
                    p.C[(long)m * p.ldc + nn] = p.e4[(long)m * p.e4ld + nn] * z * sigf(z);
                }
            }
        }
    }
}

// ---------------- split-K reduce + fused epilogue (modes 1 and 3, N=768) ----------------
__global__ void reduce_epi_kernel(const float* __restrict__ part,
                                  const float* __restrict__ bias,
                                  const float* __restrict__ e1, int e1ld,
                                  const float* __restrict__ e2,
                                  const float* __restrict__ mask,
                                  float* __restrict__ C, int mode) {
    int m = blockIdx.x, t = threadIdx.x;
    float mk = mask[m];
    const long MN = (long)MROWS * DIMD;
#pragma unroll
    for (int c = 0; c < 3; c++) {
        int n = t + c * 256;
        long idx = (long)m * DIMD + n;
        float z = part[idx] + part[MN + idx] + part[2 * MN + idx];
        float s = e1[(long)m * e1ld + n];
        float r;
        if (mode == 1) {
            z += bias[n];
            r = (z * s * mk * mk + e2[idx]) * mk;
        } else {
            float t0 = z * mk;
            float t1 = t0 * s * mk * mk;
            r = ((t1 + e2[idx]) * mk) * mk;
        }
        C[idx] = r;
    }
}

// ---------------- host launch ----------------
extern "C" void kernel_launch(void* const* d_in, const int* in_sizes, int n_in,
                              void* d_out, int out_size) {
    const float* x         = (const float*)d_in[0];
    const float* pair_rep  = (const float*)d_in[1];
    const float* cond      = (const float*)d_in[2];
    const float* mask      = (const float*)d_in[3];
    const float* pair_mask = (const float*)d_in[4];
    const float* adaln1_gw = (const float*)d_in[5];
    const float* adaln1_gb = (const float*)d_in[6];
    const float* adaln1_bw = (const float*)d_in[7];
    const float* wq = (const float*)d_in[8],  *bq = (const float*)d_in[9];
    const float* wk = (const float*)d_in[10], *bk = (const float*)d_in[11];
    const float* wv = (const float*)d_in[12], *bv = (const float*)d_in[13];
    const float* wg = (const float*)d_in[14], *bg = (const float*)d_in[15];
    const float* wb_pair = (const float*)d_in[16];
    const float* wo = (const float*)d_in[17], *bo = (const float*)d_in[18];
    const float* scale1_w = (const float*)d_in[19], *scale1_b = (const float*)d_in[20];
    const float* adaln2_gw = (const float*)d_in[21], *adaln2_gb = (const float*)d_in[22];
    const float* adaln2_bw = (const float*)d_in[23];
    const float* tr_win  = (const float*)d_in[24];
    const float* tr_wout = (const float*)d_in[25];
    const float* scale2_w = (const float*)d_in[26], *scale2_b = (const float*)d_in[27];

    float* S = nullptr;
    cudaGetSymbolAddress((void**)&S, g_scratch);
    float* cn       = S + OFF_CN;
    float* cond_out = S + OFF_COND;
    float* xm       = S + OFF_XM;
    float* xa       = S + OFF_XA;
    float* qkvg     = S + OFF_QKVG;
    float* qr       = S + OFF_QR;
    float* kr       = S + OFF_KR;
    float* vr       = S + OFF_VR;
    float* biasw    = S + OFF_BIAS;
    float* og       = S + OFF_OG;
    float* x1       = S + OFF_X1;
    float* xt       = S + OFF_XT;
    float* a_buf    = S + OFF_ABUF;
    float* hidden   = S + OFF_HID;
    float* part     = S + OFF_PART;

    // 1. LN(cond)
    ln_cond_kernel<<<MROWS, 256>>>(cond, cn);

    // 2. six cond projections in one GEMM: [g1|b1|s1|g2|b2|s2]
    {
        GemmP p = {};
        p.A = cn; p.lda = DCND; p.ldb = DIMD;
        p.Bp[0] = adaln1_gw; p.Bp[1] = adaln1_bw; p.Bp[2] = scale1_w;
        p.Bp[3] = adaln2_gw; p.Bp[4] = adaln2_bw; p.Bp[5] = scale2_w;
        p.biasp[0] = adaln1_gb; p.biasp[1] = nullptr; p.biasp[2] = scale1_b;
        p.biasp[3] = adaln2_gb; p.biasp[4] = nullptr; p.biasp[5] = scale2_b;
        p.sig[0] = 1; p.sig[1] = 0; p.sig[2] = 1; p.sig[3] = 1; p.sig[4] = 0; p.sig[5] = 1;
        p.multi = 1; p.C = cond_out; p.ldc = 6 * DIMD;
        p.M = MROWS; p.N = 6 * DIMD; p.K = DCND; p.mode = 0; p.splitk = 1;
        gemm2_kernel<<<dim3((6 * DIMD) / GBN, MROWS / GBM, 1), 256>>>(p);
    }

    // 3. xa = adaln1(x)
    adaln_kernel<<<MROWS, 256>>>(x, mask, cond_out, cond_out + DIMD, xm, xa, 1);

    // 4. QKVG projection (gate block sigmoided in epilogue)
    {
        GemmP p = {};
        p.A = xa; p.lda = DIMD; p.ldb = DIMD;
        p.Bp[0] = wq; p.Bp[1] = wk; p.Bp[2] = wv; p.Bp[3] = wg;
        p.biasp[0] = bq; p.biasp[1] = bk; p.biasp[2] = bv; p.biasp[3] = bg;
        p.sig[0] = 0; p.sig[1] = 0; p.sig[2] = 0; p.sig[3] = 1;
        p.multi = 1; p.C = qkvg; p.ldc = 4 * DIMD;
        p.M = MROWS; p.N = 4 * DIMD; p.K = DIMD; p.mode = 0; p.splitk = 1;
        gemm2_kernel<<<dim3((4 * DIMD) / GBN, MROWS / GBM, 1), 256>>>(p);
    }

    // 5. per-head LN + RoPE
    qkrope_kernel<<<MROWS, 384>>>(qkvg, qr, kr, vr);

    // 6. windowed pair bias
    pairbias_kernel<<<BB * NWW * NQ, 128>>>(pair_rep, wb_pair, biasw);

    // 7. windowed attention + gating
    attn_kernel<<<BB * HH * NWW, 256>>>(qr, kr, vr, pair_mask, biasw, qkvg, og);

    // 8. wo GEMM split-K=3 -> partials, then reduce+epilogue (mode 1) -> x1
    {
        GemmP p = {};
        p.A = og; p.lda = DIMD; p.ldb = DIMD;
        p.Bp[0] = wo; p.multi = 0;
        p.C = part; p.ldc = DIMD;
        p.M = MROWS; p.N = DIMD; p.K = DIMD; p.mode = 0; p.splitk = 3;
        gemm2_kernel<<<dim3(DIMD / GBN, MROWS / GBM, 3), 256>>>(p);
        reduce_epi_kernel<<<MROWS, 256>>>(part, bo, cond_out + 2 * DIMD, 6 * DIMD,
                                          xm, mask, x1, 1);
    }

    // 9. xt = adaln2(x1)
    adaln_kernel<<<MROWS, 256>>>(x1, mask, cond_out + 3 * DIMD, cond_out + 4 * DIMD, nullptr, xt, 0);

    // 10. transition in: a = xt @ W_a
    {
        GemmP p = {};
        p.A = xt; p.lda = DIMD; p.ldb = 2 * INR;
        p.Bp[0] = tr_win; p.multi = 0;
        p.C = a_buf; p.ldc = INR;
        p.M = MROWS; p.N = INR; p.K = DIMD; p.mode = 0; p.splitk = 1;
        gemm2_kernel<<<dim3(INR / GBN, MROWS / GBM, 1), 256>>>(p);
    }
    // 11. g = xt @ W_g ; hidden = a * silu(g)
    {
        GemmP p = {};
        p.A = xt; p.lda = DIMD; p.ldb = 2 * INR;
        p.Bp[0] = tr_win + INR; p.multi = 0;
        p.C = hidden; p.ldc = INR;
        p.M = MROWS; p.N = INR; p.K = DIMD; p.mode = 2; p.splitk = 1;
        p.e4 = a_buf; p.e4ld = INR;
        gemm2_kernel<<<dim3(INR / GBN, MROWS / GBM, 1), 256>>>(p);
    }
    // 12. transition out split-K=3 -> partials, then reduce+epilogue (mode 3) -> d_out
    {
        GemmP p = {};
        p.A = hidden; p.lda = INR; p.ldb = DIMD;
        p.Bp[0] = tr_wout; p.multi = 0;
        p.C = part; p.ldc = DIMD;
        p.M = MROWS; p.N = DIMD; p.K = INR; p.mode = 0; p.splitk = 3;
        gemm2_kernel<<<dim3(DIMD / GBN, MROWS / GBM, 3), 256>>>(p);
        reduce_epi_kernel<<<MROWS, 256>>>(part, nullptr, cond_out + 5 * DIMD, 6 * DIMD,
                                          x1, mask, (float*)d_out, 3);
    }
}